// round 9
// baseline (speedup 1.0000x reference)
#include <cuda_runtime.h>
#include <math.h>

#define N_NODES   100000
#define N_EDGES   1600000
#define IN_FEAT   128
#define N_HEADS   8
#define OUT_FEAT  16
#define HF        128
#define NEG_SLOPE 0.2f

#define SCAN_B    512
#define NB1       ((N_NODES + SCAN_B - 1) / SCAN_B)   // 196

typedef unsigned long long u64;

// ---------------- device scratch ----------------
__device__ float d_h   [N_NODES * HF];
__device__ float d_q   [N_NODES * N_HEADS];
__device__ float d_kk  [N_NODES * N_HEADS];
__device__ int   d_deg [N_NODES];
__device__ int   d_off [N_NODES];
__device__ int   d_pos [N_NODES];
__device__ int   d_csrc[N_EDGES];
__device__ int   d_bsum[NB1];
__device__ int   d_bsum2[NB1];

__device__ __forceinline__ void ffma2(u64& acc, u64 a, u64 b) {
    asm("fma.rn.f32x2 %0, %1, %2, %0;" : "+l"(acc) : "l"(a), "l"(b));
}
__device__ __forceinline__ u64 pack2(float lo, float hi) {
    u64 r;
    asm("mov.b64 %0, {%1, %2};" : "=l"(r) : "f"(lo), "f"(hi));
    return r;
}
__device__ __forceinline__ void unpack2(float& lo, float& hi, u64 v) {
    asm("mov.b64 {%0, %1}, %2;" : "=f"(lo), "=f"(hi) : "l"(v));
}

// ---------------- K0: init ----------------
__global__ void k_init() {
    int i = blockIdx.x * blockDim.x + threadIdx.x;
    if (i < N_NODES) d_deg[i] = 0;
}

// ---------------- K1: tiled GEMM  h = x @ Wv + bv  (FFMA2 inner loop) ----
// BM=64 nodes, BN=128 (full), BK=16, 256 threads.
// Thread (tx,ty): rows ty*8..ty*8+7 (paired), cols tx*4..tx*4+3 (dup-packed W).
#define BM 64
#define BK 16
__global__ __launch_bounds__(256) void k_gemm(const float* __restrict__ x,
                                              const float* __restrict__ Wv,
                                              const float* __restrict__ bv) {
    __shared__ float Xs[BK][BM + 2];     // stride 264B -> u64-aligned rows
    __shared__ float Wd[BK][2 * HF];     // duplicated cols: (w,w) pairs, 16KB

    const int tid = threadIdx.x;
    const int tx  = tid & 31;
    const int ty  = tid >> 5;
    const int bm  = blockIdx.x * BM;

    u64 accp[4][4];                      // [row-pair p][col j] = (acc[2p][j], acc[2p+1][j])
    const u64 zero = 0;
#pragma unroll
    for (int p = 0; p < 4; ++p)
#pragma unroll
        for (int j = 0; j < 4; ++j) accp[p][j] = zero;

    for (int k0 = 0; k0 < IN_FEAT; k0 += BK) {
#pragma unroll
        for (int i = 0; i < 4; ++i) {
            int idx = tid + i * 256;
            int nl  = idx >> 4;
            int kk  = idx & 15;
            int node = bm + nl;
            Xs[kk][nl] = (node < N_NODES) ? x[(size_t)node * IN_FEAT + k0 + kk] : 0.0f;
        }
#pragma unroll
        for (int i = 0; i < 8; ++i) {
            int idx = tid + i * 256;
            int kk  = idx >> 7;
            int f   = idx & 127;
            float w = Wv[(size_t)(k0 + kk) * HF + f];
            *(u64*)&Wd[kk][2 * f] = pack2(w, w);
        }
        __syncthreads();

#pragma unroll
        for (int kk = 0; kk < BK; ++kk) {
            const u64* wp = (const u64*)&Wd[kk][tx * 8];   // 4 dup pairs (cols)
            const u64* xp = (const u64*)&Xs[kk][ty * 8];   // 4 row pairs
            u64 w0 = wp[0], w1 = wp[1], w2 = wp[2], w3 = wp[3];
            u64 x0 = xp[0], x1 = xp[1], x2 = xp[2], x3 = xp[3];
            ffma2(accp[0][0], w0, x0); ffma2(accp[0][1], w1, x0);
            ffma2(accp[0][2], w2, x0); ffma2(accp[0][3], w3, x0);
            ffma2(accp[1][0], w0, x1); ffma2(accp[1][1], w1, x1);
            ffma2(accp[1][2], w2, x1); ffma2(accp[1][3], w3, x1);
            ffma2(accp[2][0], w0, x2); ffma2(accp[2][1], w1, x2);
            ffma2(accp[2][2], w2, x2); ffma2(accp[2][3], w3, x2);
            ffma2(accp[3][0], w0, x3); ffma2(accp[3][1], w1, x3);
            ffma2(accp[3][2], w2, x3); ffma2(accp[3][3], w3, x3);
        }
        __syncthreads();
    }

    float4 bias = *(const float4*)&bv[tx * 4];
#pragma unroll
    for (int p = 0; p < 4; ++p) {
        float lo[4], hi[4];
#pragma unroll
        for (int j = 0; j < 4; ++j) unpack2(lo[j], hi[j], accp[p][j]);

        int node0 = bm + ty * 8 + 2 * p;
        if (node0 < N_NODES) {
            float4 r;
            r.x = lo[0] + bias.x; r.y = lo[1] + bias.y;
            r.z = lo[2] + bias.z; r.w = lo[3] + bias.w;
            *(float4*)&d_h[(size_t)node0 * HF + tx * 4] = r;
        }
        int node1 = node0 + 1;
        if (node1 < N_NODES) {
            float4 r;
            r.x = hi[0] + bias.x; r.y = hi[1] + bias.y;
            r.z = hi[2] + bias.z; r.w = hi[3] + bias.w;
            *(float4*)&d_h[(size_t)node1 * HF + tx * 4] = r;
        }
    }
}

// ---------------- K2: q/k projections ----------------
__global__ __launch_bounds__(128) void k_qk(const float* __restrict__ Wq,
                                            const float* __restrict__ bq,
                                            const float* __restrict__ Wk,
                                            const float* __restrict__ bk) {
    __shared__ float hs[8][HF];
    __shared__ float Wqs[HF * N_HEADS];
    __shared__ float Wks[HF * N_HEADS];

    const int t = threadIdx.x;
    const int nb = blockIdx.x * 8;

#pragma unroll
    for (int i = 0; i < 8; ++i) {
        int idx = t + i * 128;
        Wqs[idx] = Wq[idx];
        Wks[idx] = Wk[idx];
    }
#pragma unroll
    for (int i = 0; i < 8; ++i) {
        int idx = t + i * 128;
        int nl = idx >> 7;
        int j  = idx & 127;
        int node = nb + nl;
        hs[nl][j] = (node < N_NODES) ? d_h[(size_t)node * HF + j] : 0.0f;
    }
    __syncthreads();

    const int nl  = t >> 4;
    const int id  = t & 15;
    const int hd  = id & 7;
    const bool isQ = (id < 8);
    const int node = nb + nl;
    if (node >= N_NODES) return;

    const float* W = isQ ? Wqs : Wks;
    float s = isQ ? bq[hd] : bk[hd];
#pragma unroll 16
    for (int j = 0; j < HF; ++j)
        s = fmaf(hs[nl][j], W[j * N_HEADS + hd], s);

    if (isQ) d_q [node * N_HEADS + hd] = s;
    else     d_kk[node * N_HEADS + hd] = s;
}

// ---------------- CSR build ----------------
__global__ void k_count(const int* __restrict__ dst) {
    int i = blockIdx.x * blockDim.x + threadIdx.x;
    if (i >= N_EDGES / 4) return;
    int4 d = ((const int4*)dst)[i];
    atomicAdd(&d_deg[d.x], 1);
    atomicAdd(&d_deg[d.y], 1);
    atomicAdd(&d_deg[d.z], 1);
    atomicAdd(&d_deg[d.w], 1);
}

__global__ __launch_bounds__(SCAN_B) void k_scan1() {
    __shared__ int tmp[2][SCAN_B];
    const int t = threadIdx.x;
    const int i = blockIdx.x * SCAN_B + t;
    int v = (i < N_NODES) ? d_deg[i] : 0;
    tmp[0][t] = v;
    __syncthreads();
    int pp = 0;
    for (int off = 1; off < SCAN_B; off <<= 1) {
        int xv = tmp[pp][t];
        if (t >= off) xv += tmp[pp][t - off];
        tmp[pp ^ 1][t] = xv;
        pp ^= 1;
        __syncthreads();
    }
    int incl = tmp[pp][t];
    if (i < N_NODES) d_off[i] = incl - v;
    if (t == SCAN_B - 1) d_bsum[blockIdx.x] = incl;
}

__global__ __launch_bounds__(256) void k_scan2() {
    __shared__ int tmp[2][256];
    const int t = threadIdx.x;
    int v = (t < NB1) ? d_bsum[t] : 0;
    tmp[0][t] = v;
    __syncthreads();
    int pp = 0;
    for (int off = 1; off < 256; off <<= 1) {
        int xv = tmp[pp][t];
        if (t >= off) xv += tmp[pp][t - off];
        tmp[pp ^ 1][t] = xv;
        pp ^= 1;
        __syncthreads();
    }
    if (t < NB1) d_bsum2[t] = tmp[pp][t] - v;
}

__global__ __launch_bounds__(SCAN_B) void k_scan3() {
    const int i = blockIdx.x * SCAN_B + threadIdx.x;
    if (i < N_NODES) {
        int o = d_off[i] + d_bsum2[blockIdx.x];
        d_off[i] = o;
        d_pos[i] = o;
    }
}

__global__ void k_fill(const int* __restrict__ src, const int* __restrict__ dst) {
    int i = blockIdx.x * blockDim.x + threadIdx.x;
    if (i >= N_EDGES / 4) return;
    int4 d = ((const int4*)dst)[i];
    int4 s = ((const int4*)src)[i];
    d_csrc[atomicAdd(&d_pos[d.x], 1)] = s.x;
    d_csrc[atomicAdd(&d_pos[d.y], 1)] = s.y;
    d_csrc[atomicAdd(&d_pos[d.z], 1)] = s.z;
    d_csrc[atomicAdd(&d_pos[d.w], 1)] = s.w;
}

// ---------------- K3: fused softmax + aggregate + normalize + head-mean ----
__device__ __forceinline__ void agg_edge(int s, int hd, int l, float qv,
                                         float4& acc, float& den) {
    const float kk = d_kk[s * N_HEADS + hd];
    const float4 hv = *(const float4*)&d_h[(size_t)s * HF + l * 4];
    float c = kk + qv; c = (c >= 0.f) ? c : NEG_SLOPE * c;
    const float e = __expf(c);
    acc.x = fmaf(e, hv.x, acc.x); acc.y = fmaf(e, hv.y, acc.y);
    acc.z = fmaf(e, hv.z, acc.z); acc.w = fmaf(e, hv.w, acc.w);
    den += e;
}

__global__ __launch_bounds__(128) void k_agg(float* __restrict__ out) {
    const int n = blockIdx.x * 4 + (threadIdx.x >> 5);
    if (n >= N_NODES) return;
    const int l  = threadIdx.x & 31;
    const int hd = l >> 2;

    const float qv    = d_q[n * N_HEADS + hd];
    const int   start = d_off[n];
    const int   deg   = d_deg[n];

    float4 acc = make_float4(0.f, 0.f, 0.f, 0.f);
    float  den = 0.f;

    int j = 0;
    for (; j + 3 < deg; j += 4) {
        const int s0 = d_csrc[start + j];
        const int s1 = d_csrc[start + j + 1];
        const int s2 = d_csrc[start + j + 2];
        const int s3 = d_csrc[start + j + 3];
        agg_edge(s0, hd, l, qv, acc, den);
        agg_edge(s1, hd, l, qv, acc, den);
        agg_edge(s2, hd, l, qv, acc, den);
        agg_edge(s3, hd, l, qv, acc, den);
    }
    for (; j < deg; ++j)
        agg_edge(d_csrc[start + j], hd, l, qv, acc, den);

    const float inv = (deg > 0) ? 1.0f / den : 0.0f;
    acc.x *= inv; acc.y *= inv; acc.z *= inv; acc.w *= inv;

#pragma unroll
    for (int off = 4; off < 32; off <<= 1) {
        acc.x += __shfl_xor_sync(0xffffffff, acc.x, off);
        acc.y += __shfl_xor_sync(0xffffffff, acc.y, off);
        acc.z += __shfl_xor_sync(0xffffffff, acc.z, off);
        acc.w += __shfl_xor_sync(0xffffffff, acc.w, off);
    }

    if (l < 4) {
        float4 r;
        r.x = acc.x * (1.0f / N_HEADS);
        r.y = acc.y * (1.0f / N_HEADS);
        r.z = acc.z * (1.0f / N_HEADS);
        r.w = acc.w * (1.0f / N_HEADS);
        *(float4*)&out[(size_t)n * OUT_FEAT + l * 4] = r;
    }
}

// ---------------- launch ----------------
extern "C" void kernel_launch(void* const* d_in, const int* in_sizes, int n_in,
                              void* d_out, int out_size) {
    const float* x   = (const float*)d_in[0];
    const int*   src = (const int*)d_in[1];
    const int*   dst = (const int*)d_in[2];
    const float* Wv  = (const float*)d_in[3];
    const float* bv  = (const float*)d_in[4];
    const float* Wq  = (const float*)d_in[5];
    const float* bq  = (const float*)d_in[6];
    const float* Wk  = (const float*)d_in[7];
    const float* bk  = (const float*)d_in[8];
    float* out = (float*)d_out;

    k_init <<<(N_NODES + 255) / 256, 256>>>();
    k_gemm <<<(N_NODES + BM - 1) / BM, 256>>>(x, Wv, bv);
    k_qk   <<<(N_NODES + 7) / 8, 128>>>(Wq, bq, Wk, bk);
    k_count<<<(N_EDGES / 4 + 255) / 256, 256>>>(dst);
    k_scan1<<<NB1, SCAN_B>>>();
    k_scan2<<<1, 256>>>();
    k_scan3<<<NB1, SCAN_B>>>();
    k_fill <<<(N_EDGES / 4 + 255) / 256, 256>>>(src, dst);
    k_agg  <<<(N_NODES + 3) / 4, 128>>>(out);
}

// round 10
// speedup vs baseline: 1.5004x; 1.5004x over previous
#include <cuda_runtime.h>
#include <math.h>

#define N_NODES   100000
#define N_EDGES   1600000
#define IN_FEAT   128
#define N_HEADS   8
#define OUT_FEAT  16
#define HF        128
#define NEG_SLOPE 0.2f

#define SCAN_B    512
#define NB1       ((N_NODES + SCAN_B - 1) / SCAN_B)   // 196

// ---------------- device scratch ----------------
__device__ float d_h   [N_NODES * HF];
__device__ float d_q   [N_NODES * N_HEADS];
__device__ float d_kk  [N_NODES * N_HEADS];
__device__ int   d_deg [N_NODES];
__device__ int   d_off [N_NODES];
__device__ int   d_pos [N_NODES];
__device__ int   d_csrc[N_EDGES];
__device__ int   d_bsum[NB1];
__device__ int   d_bsum2[NB1];

// ---------------- K0: init ----------------
__global__ void k_init() {
    int i = blockIdx.x * blockDim.x + threadIdx.x;
    if (i < N_NODES) d_deg[i] = 0;
}

// ---------------- helpers ----------------
__device__ __forceinline__ unsigned f2tf(float f) {
    unsigned r;
    asm("cvt.rna.tf32.f32 %0, %1;" : "=r"(r) : "f"(f));
    return r;
}

// ---------------- K1: tf32 tensor-core GEMM  h = x @ Wv + bv ----------------
// Block tile 128(M) x 128(N), BK=32 chunks, 8 warps (warp tile 32x64).
// mma.sync.aligned.m16n8k8.row.col.f32.tf32.tf32.f32
#define GBM 128
#define GBK 32
__global__ __launch_bounds__(256) void k_gemm(const float* __restrict__ x,
                                              const float* __restrict__ Wv,
                                              const float* __restrict__ bv) {
    __shared__ float Xs[GBM][36];    // stride 36: bank = 4r+c, conflict-free frags
    __shared__ float Ws[GBK][136];   // stride 136: bank = 8r+c, conflict-free frags

    const int tid  = threadIdx.x;
    const int lane = tid & 31;
    const int warp = tid >> 5;
    const int bm   = blockIdx.x * GBM;

    const int warp_m = (warp & 3) * 32;   // 4 warps tile M
    const int warp_n = (warp >> 2) * 64;  // 2 warps tile N

    const int lq = lane >> 2;   // 0..7
    const int lr = lane & 3;    // 0..3

    float c[2][8][4];
#pragma unroll
    for (int mt = 0; mt < 2; ++mt)
#pragma unroll
        for (int nt = 0; nt < 8; ++nt)
#pragma unroll
            for (int j = 0; j < 4; ++j) c[mt][nt][j] = 0.0f;

    for (int k0 = 0; k0 < IN_FEAT; k0 += GBK) {
        // load X chunk: 128 rows x 32 cols = 1024 float4
#pragma unroll
        for (int i = 0; i < 4; ++i) {
            int fid = tid + i * 256;
            int row = fid >> 3;
            int c4  = fid & 7;
            int node = bm + row;
            float4 v = make_float4(0.f, 0.f, 0.f, 0.f);
            if (node < N_NODES)
                v = *(const float4*)&x[(size_t)node * IN_FEAT + k0 + c4 * 4];
            float4 t;
            t.x = __uint_as_float(f2tf(v.x));
            t.y = __uint_as_float(f2tf(v.y));
            t.z = __uint_as_float(f2tf(v.z));
            t.w = __uint_as_float(f2tf(v.w));
            *(float4*)&Xs[row][c4 * 4] = t;
        }
        // load W chunk: 32 rows x 128 cols = 1024 float4
#pragma unroll
        for (int i = 0; i < 4; ++i) {
            int fid = tid + i * 256;
            int row = fid >> 5;
            int c4  = fid & 31;
            float4 v = *(const float4*)&Wv[(size_t)(k0 + row) * HF + c4 * 4];
            float4 t;
            t.x = __uint_as_float(f2tf(v.x));
            t.y = __uint_as_float(f2tf(v.y));
            t.z = __uint_as_float(f2tf(v.z));
            t.w = __uint_as_float(f2tf(v.w));
            *(float4*)&Ws[row][c4 * 4] = t;
        }
        __syncthreads();

#pragma unroll
        for (int ks = 0; ks < GBK / 8; ++ks) {
            const int kc = ks * 8;
            unsigned a[2][4];
#pragma unroll
            for (int mt = 0; mt < 2; ++mt) {
                const int m0 = warp_m + mt * 16;
                a[mt][0] = __float_as_uint(Xs[m0 + lq    ][kc + lr    ]);
                a[mt][1] = __float_as_uint(Xs[m0 + 8 + lq][kc + lr    ]);
                a[mt][2] = __float_as_uint(Xs[m0 + lq    ][kc + 4 + lr]);
                a[mt][3] = __float_as_uint(Xs[m0 + 8 + lq][kc + 4 + lr]);
            }
#pragma unroll
            for (int nt = 0; nt < 8; ++nt) {
                const int n0 = warp_n + nt * 8;
                unsigned b0 = __float_as_uint(Ws[kc + lr    ][n0 + lq]);
                unsigned b1 = __float_as_uint(Ws[kc + 4 + lr][n0 + lq]);
#pragma unroll
                for (int mt = 0; mt < 2; ++mt) {
                    asm volatile(
                        "mma.sync.aligned.m16n8k8.row.col.f32.tf32.tf32.f32 "
                        "{%0,%1,%2,%3}, {%4,%5,%6,%7}, {%8,%9}, {%0,%1,%2,%3};\n"
                        : "+f"(c[mt][nt][0]), "+f"(c[mt][nt][1]),
                          "+f"(c[mt][nt][2]), "+f"(c[mt][nt][3])
                        : "r"(a[mt][0]), "r"(a[mt][1]), "r"(a[mt][2]), "r"(a[mt][3]),
                          "r"(b0), "r"(b1));
                }
            }
        }
        __syncthreads();
    }

    // epilogue: c[mt][nt]: (row = lq (+8), col = 2*lr + {0,1}) within 16x8 tile
#pragma unroll
    for (int nt = 0; nt < 8; ++nt) {
        const int col = warp_n + nt * 8 + lr * 2;
        const float2 bias = *(const float2*)&bv[col];
#pragma unroll
        for (int mt = 0; mt < 2; ++mt) {
            const int r0 = bm + warp_m + mt * 16 + lq;
            if (r0 < N_NODES) {
                float2 v = make_float2(c[mt][nt][0] + bias.x, c[mt][nt][1] + bias.y);
                *(float2*)&d_h[(size_t)r0 * HF + col] = v;
            }
            const int r1 = r0 + 8;
            if (r1 < N_NODES) {
                float2 v = make_float2(c[mt][nt][2] + bias.x, c[mt][nt][3] + bias.y);
                *(float2*)&d_h[(size_t)r1 * HF + col] = v;
            }
        }
    }
}

// ---------------- K2: q/k projections ----------------
__global__ __launch_bounds__(128) void k_qk(const float* __restrict__ Wq,
                                            const float* __restrict__ bq,
                                            const float* __restrict__ Wk,
                                            const float* __restrict__ bk) {
    __shared__ float hs[8][HF];
    __shared__ float Wqs[HF * N_HEADS];
    __shared__ float Wks[HF * N_HEADS];

    const int t = threadIdx.x;
    const int nb = blockIdx.x * 8;

#pragma unroll
    for (int i = 0; i < 8; ++i) {
        int idx = t + i * 128;
        Wqs[idx] = Wq[idx];
        Wks[idx] = Wk[idx];
    }
#pragma unroll
    for (int i = 0; i < 8; ++i) {
        int idx = t + i * 128;
        int nl = idx >> 7;
        int j  = idx & 127;
        int node = nb + nl;
        hs[nl][j] = (node < N_NODES) ? d_h[(size_t)node * HF + j] : 0.0f;
    }
    __syncthreads();

    const int nl  = t >> 4;
    const int id  = t & 15;
    const int hd  = id & 7;
    const bool isQ = (id < 8);
    const int node = nb + nl;
    if (node >= N_NODES) return;

    const float* W = isQ ? Wqs : Wks;
    float s = isQ ? bq[hd] : bk[hd];
#pragma unroll 16
    for (int j = 0; j < HF; ++j)
        s = fmaf(hs[nl][j], W[j * N_HEADS + hd], s);

    if (isQ) d_q [node * N_HEADS + hd] = s;
    else     d_kk[node * N_HEADS + hd] = s;
}

// ---------------- CSR build ----------------
__global__ void k_count(const int* __restrict__ dst) {
    int e = blockIdx.x * blockDim.x + threadIdx.x;
    if (e < N_EDGES) atomicAdd(&d_deg[dst[e]], 1);
}

__global__ __launch_bounds__(SCAN_B) void k_scan1() {
    __shared__ int tmp[2][SCAN_B];
    const int t = threadIdx.x;
    const int i = blockIdx.x * SCAN_B + t;
    int v = (i < N_NODES) ? d_deg[i] : 0;
    tmp[0][t] = v;
    __syncthreads();
    int pp = 0;
    for (int off = 1; off < SCAN_B; off <<= 1) {
        int xv = tmp[pp][t];
        if (t >= off) xv += tmp[pp][t - off];
        tmp[pp ^ 1][t] = xv;
        pp ^= 1;
        __syncthreads();
    }
    int incl = tmp[pp][t];
    if (i < N_NODES) d_off[i] = incl - v;
    if (t == SCAN_B - 1) d_bsum[blockIdx.x] = incl;
}

__global__ __launch_bounds__(256) void k_scan2() {
    __shared__ int tmp[2][256];
    const int t = threadIdx.x;
    int v = (t < NB1) ? d_bsum[t] : 0;
    tmp[0][t] = v;
    __syncthreads();
    int pp = 0;
    for (int off = 1; off < 256; off <<= 1) {
        int xv = tmp[pp][t];
        if (t >= off) xv += tmp[pp][t - off];
        tmp[pp ^ 1][t] = xv;
        pp ^= 1;
        __syncthreads();
    }
    if (t < NB1) d_bsum2[t] = tmp[pp][t] - v;
}

__global__ __launch_bounds__(SCAN_B) void k_scan3() {
    const int i = blockIdx.x * SCAN_B + threadIdx.x;
    if (i < N_NODES) {
        int o = d_off[i] + d_bsum2[blockIdx.x];
        d_off[i] = o;
        d_pos[i] = o;
    }
}

__global__ void k_fill(const int* __restrict__ src, const int* __restrict__ dst) {
    int e = blockIdx.x * blockDim.x + threadIdx.x;
    if (e >= N_EDGES) return;
    int p = atomicAdd(&d_pos[dst[e]], 1);
    d_csrc[p] = src[e];
}

// ---------------- K3: fused softmax + aggregate + normalize + head-mean ----
__device__ __forceinline__ void agg_edge(int s, int hd, int l, float qv,
                                         float4& acc, float& den) {
    const float kk = d_kk[s * N_HEADS + hd];
    const float4 hv = *(const float4*)&d_h[(size_t)s * HF + l * 4];
    float c = kk + qv; c = (c >= 0.f) ? c : NEG_SLOPE * c;
    const float e = __expf(c);
    acc.x = fmaf(e, hv.x, acc.x); acc.y = fmaf(e, hv.y, acc.y);
    acc.z = fmaf(e, hv.z, acc.z); acc.w = fmaf(e, hv.w, acc.w);
    den += e;
}

__global__ __launch_bounds__(128) void k_agg(float* __restrict__ out) {
    const int n = blockIdx.x * 4 + (threadIdx.x >> 5);
    if (n >= N_NODES) return;
    const int l  = threadIdx.x & 31;
    const int hd = l >> 2;

    const float qv    = d_q[n * N_HEADS + hd];
    const int   start = d_off[n];
    const int   deg   = d_deg[n];

    float4 acc = make_float4(0.f, 0.f, 0.f, 0.f);
    float  den = 0.f;

    int j = 0;
    for (; j + 3 < deg; j += 4) {
        const int s0 = d_csrc[start + j];
        const int s1 = d_csrc[start + j + 1];
        const int s2 = d_csrc[start + j + 2];
        const int s3 = d_csrc[start + j + 3];
        agg_edge(s0, hd, l, qv, acc, den);
        agg_edge(s1, hd, l, qv, acc, den);
        agg_edge(s2, hd, l, qv, acc, den);
        agg_edge(s3, hd, l, qv, acc, den);
    }
    for (; j < deg; ++j)
        agg_edge(d_csrc[start + j], hd, l, qv, acc, den);

    const float inv = (deg > 0) ? 1.0f / den : 0.0f;
    acc.x *= inv; acc.y *= inv; acc.z *= inv; acc.w *= inv;

#pragma unroll
    for (int off = 4; off < 32; off <<= 1) {
        acc.x += __shfl_xor_sync(0xffffffff, acc.x, off);
        acc.y += __shfl_xor_sync(0xffffffff, acc.y, off);
        acc.z += __shfl_xor_sync(0xffffffff, acc.z, off);
        acc.w += __shfl_xor_sync(0xffffffff, acc.w, off);
    }

    if (l < 4) {
        float4 r;
        r.x = acc.x * (1.0f / N_HEADS);
        r.y = acc.y * (1.0f / N_HEADS);
        r.z = acc.z * (1.0f / N_HEADS);
        r.w = acc.w * (1.0f / N_HEADS);
        *(float4*)&out[(size_t)n * OUT_FEAT + l * 4] = r;
    }
}

// ---------------- launch ----------------
extern "C" void kernel_launch(void* const* d_in, const int* in_sizes, int n_in,
                              void* d_out, int out_size) {
    const float* x   = (const float*)d_in[0];
    const int*   src = (const int*)d_in[1];
    const int*   dst = (const int*)d_in[2];
    const float* Wv  = (const float*)d_in[3];
    const float* bv  = (const float*)d_in[4];
    const float* Wq  = (const float*)d_in[5];
    const float* bq  = (const float*)d_in[6];
    const float* Wk  = (const float*)d_in[7];
    const float* bk  = (const float*)d_in[8];
    float* out = (float*)d_out;

    k_init <<<(N_NODES + 255) / 256, 256>>>();
    k_gemm <<<(N_NODES + GBM - 1) / GBM, 256>>>(x, Wv, bv);
    k_qk   <<<(N_NODES + 7) / 8, 128>>>(Wq, bq, Wk, bk);
    k_count<<<(N_EDGES + 255) / 256, 256>>>(dst);
    k_scan1<<<NB1, SCAN_B>>>();
    k_scan2<<<1, 256>>>();
    k_scan3<<<NB1, SCAN_B>>>();
    k_fill <<<(N_EDGES + 255) / 256, 256>>>(src, dst);
    k_agg  <<<(N_NODES + 3) / 4, 128>>>(out);
}

// round 13
// speedup vs baseline: 1.5828x; 1.0549x over previous
#include <cuda_runtime.h>
#include <math.h>

#define N_NODES   100000
#define N_EDGES   1600000
#define IN_FEAT   128
#define N_HEADS   8
#define OUT_FEAT  16
#define HF        128
#define NEG_SLOPE 0.2f

#define SCAN_B    512
#define NB1       ((N_NODES + SCAN_B - 1) / SCAN_B)   // 196

// ---------------- device scratch ----------------
__device__ float d_h   [N_NODES * HF];
__device__ float d_q   [N_NODES * N_HEADS];
__device__ float d_kk  [N_NODES * N_HEADS];
__device__ int   d_deg [N_NODES];
__device__ int   d_off [N_NODES];
__device__ int   d_pos [N_NODES];
__device__ int   d_csrc[N_EDGES];
__device__ int   d_bsum[NB1];
__device__ int   d_bsum2[NB1];

// ---------------- K0: init ----------------
__global__ void k_init() {
    int i = blockIdx.x * blockDim.x + threadIdx.x;
    if (i < N_NODES) d_deg[i] = 0;
}

// ---------------- helpers ----------------
__device__ __forceinline__ unsigned f2tf(float f) {
    unsigned r;
    asm("cvt.rna.tf32.f32 %0, %1;" : "=r"(r) : "f"(f));
    return r;
}

// ---------------- K1: tf32 tensor-core GEMM  h = x @ Wv + bv ----------------
#define GBM 128
#define GBK 32
__global__ __launch_bounds__(256) void k_gemm(const float* __restrict__ x,
                                              const float* __restrict__ Wv,
                                              const float* __restrict__ bv) {
    __shared__ float Xs[GBM][36];
    __shared__ float Ws[GBK][136];

    const int tid  = threadIdx.x;
    const int lane = tid & 31;
    const int warp = tid >> 5;
    const int bm   = blockIdx.x * GBM;

    const int warp_m = (warp & 3) * 32;
    const int warp_n = (warp >> 2) * 64;

    const int lq = lane >> 2;
    const int lr = lane & 3;

    float c[2][8][4];
#pragma unroll
    for (int mt = 0; mt < 2; ++mt)
#pragma unroll
        for (int nt = 0; nt < 8; ++nt)
#pragma unroll
            for (int j = 0; j < 4; ++j) c[mt][nt][j] = 0.0f;

    for (int k0 = 0; k0 < IN_FEAT; k0 += GBK) {
#pragma unroll
        for (int i = 0; i < 4; ++i) {
            int fid = tid + i * 256;
            int row = fid >> 3;
            int c4  = fid & 7;
            int node = bm + row;
            float4 v = make_float4(0.f, 0.f, 0.f, 0.f);
            if (node < N_NODES)
                v = *(const float4*)&x[(size_t)node * IN_FEAT + k0 + c4 * 4];
            float4 t;
            t.x = __uint_as_float(f2tf(v.x));
            t.y = __uint_as_float(f2tf(v.y));
            t.z = __uint_as_float(f2tf(v.z));
            t.w = __uint_as_float(f2tf(v.w));
            *(float4*)&Xs[row][c4 * 4] = t;
        }
#pragma unroll
        for (int i = 0; i < 4; ++i) {
            int fid = tid + i * 256;
            int row = fid >> 5;
            int c4  = fid & 31;
            float4 v = *(const float4*)&Wv[(size_t)(k0 + row) * HF + c4 * 4];
            float4 t;
            t.x = __uint_as_float(f2tf(v.x));
            t.y = __uint_as_float(f2tf(v.y));
            t.z = __uint_as_float(f2tf(v.z));
            t.w = __uint_as_float(f2tf(v.w));
            *(float4*)&Ws[row][c4 * 4] = t;
        }
        __syncthreads();

#pragma unroll
        for (int ks = 0; ks < GBK / 8; ++ks) {
            const int kc = ks * 8;
            unsigned a[2][4];
#pragma unroll
            for (int mt = 0; mt < 2; ++mt) {
                const int m0 = warp_m + mt * 16;
                a[mt][0] = __float_as_uint(Xs[m0 + lq    ][kc + lr    ]);
                a[mt][1] = __float_as_uint(Xs[m0 + 8 + lq][kc + lr    ]);
                a[mt][2] = __float_as_uint(Xs[m0 + lq    ][kc + 4 + lr]);
                a[mt][3] = __float_as_uint(Xs[m0 + 8 + lq][kc + 4 + lr]);
            }
#pragma unroll
            for (int nt = 0; nt < 8; ++nt) {
                const int n0 = warp_n + nt * 8;
                unsigned b0 = __float_as_uint(Ws[kc + lr    ][n0 + lq]);
                unsigned b1 = __float_as_uint(Ws[kc + 4 + lr][n0 + lq]);
#pragma unroll
                for (int mt = 0; mt < 2; ++mt) {
                    asm volatile(
                        "mma.sync.aligned.m16n8k8.row.col.f32.tf32.tf32.f32 "
                        "{%0,%1,%2,%3}, {%4,%5,%6,%7}, {%8,%9}, {%0,%1,%2,%3};\n"
                        : "+f"(c[mt][nt][0]), "+f"(c[mt][nt][1]),
                          "+f"(c[mt][nt][2]), "+f"(c[mt][nt][3])
                        : "r"(a[mt][0]), "r"(a[mt][1]), "r"(a[mt][2]), "r"(a[mt][3]),
                          "r"(b0), "r"(b1));
                }
            }
        }
        __syncthreads();
    }

#pragma unroll
    for (int nt = 0; nt < 8; ++nt) {
        const int col = warp_n + nt * 8 + lr * 2;
        const float2 bias = *(const float2*)&bv[col];
#pragma unroll
        for (int mt = 0; mt < 2; ++mt) {
            const int r0 = bm + warp_m + mt * 16 + lq;
            if (r0 < N_NODES) {
                float2 v = make_float2(c[mt][nt][0] + bias.x, c[mt][nt][1] + bias.y);
                *(float2*)&d_h[(size_t)r0 * HF + col] = v;
            }
            const int r1 = r0 + 8;
            if (r1 < N_NODES) {
                float2 v = make_float2(c[mt][nt][2] + bias.x, c[mt][nt][3] + bias.y);
                *(float2*)&d_h[(size_t)r1 * HF + col] = v;
            }
        }
    }
}

// ---------------- K2: q/k projections ----------------
__global__ __launch_bounds__(128) void k_qk(const float* __restrict__ Wq,
                                            const float* __restrict__ bq,
                                            const float* __restrict__ Wk,
                                            const float* __restrict__ bk) {
    __shared__ float hs[8][HF];
    __shared__ float Wqs[HF * N_HEADS];
    __shared__ float Wks[HF * N_HEADS];

    const int t = threadIdx.x;
    const int nb = blockIdx.x * 8;

#pragma unroll
    for (int i = 0; i < 8; ++i) {
        int idx = t + i * 128;
        Wqs[idx] = Wq[idx];
        Wks[idx] = Wk[idx];
    }
#pragma unroll
    for (int i = 0; i < 8; ++i) {
        int idx = t + i * 128;
        int nl = idx >> 7;
        int j  = idx & 127;
        int node = nb + nl;
        hs[nl][j] = (node < N_NODES) ? d_h[(size_t)node * HF + j] : 0.0f;
    }
    __syncthreads();

    const int nl  = t >> 4;
    const int id  = t & 15;
    const int hd  = id & 7;
    const bool isQ = (id < 8);
    const int node = nb + nl;
    if (node >= N_NODES) return;

    const float* W = isQ ? Wqs : Wks;
    float s = isQ ? bq[hd] : bk[hd];
#pragma unroll 16
    for (int j = 0; j < HF; ++j)
        s = fmaf(hs[nl][j], W[j * N_HEADS + hd], s);

    if (isQ) d_q [node * N_HEADS + hd] = s;
    else     d_kk[node * N_HEADS + hd] = s;
}

// ---------------- CSR build ----------------
__global__ void k_count(const int* __restrict__ dst) {
    int e = blockIdx.x * blockDim.x + threadIdx.x;
    if (e < N_EDGES) atomicAdd(&d_deg[dst[e]], 1);
}

__global__ __launch_bounds__(SCAN_B) void k_scan1() {
    __shared__ int tmp[2][SCAN_B];
    const int t = threadIdx.x;
    const int i = blockIdx.x * SCAN_B + t;
    int v = (i < N_NODES) ? d_deg[i] : 0;
    tmp[0][t] = v;
    __syncthreads();
    int pp = 0;
    for (int off = 1; off < SCAN_B; off <<= 1) {
        int xv = tmp[pp][t];
        if (t >= off) xv += tmp[pp][t - off];
        tmp[pp ^ 1][t] = xv;
        pp ^= 1;
        __syncthreads();
    }
    int incl = tmp[pp][t];
    if (i < N_NODES) d_off[i] = incl - v;
    if (t == SCAN_B - 1) d_bsum[blockIdx.x] = incl;
}

__global__ __launch_bounds__(256) void k_scan2() {
    __shared__ int tmp[2][256];
    const int t = threadIdx.x;
    int v = (t < NB1) ? d_bsum[t] : 0;
    tmp[0][t] = v;
    __syncthreads();
    int pp = 0;
    for (int off = 1; off < 256; off <<= 1) {
        int xv = tmp[pp][t];
        if (t >= off) xv += tmp[pp][t - off];
        tmp[pp ^ 1][t] = xv;
        pp ^= 1;
        __syncthreads();
    }
    if (t < NB1) d_bsum2[t] = tmp[pp][t] - v;
}

__global__ __launch_bounds__(SCAN_B) void k_scan3() {
    const int i = blockIdx.x * SCAN_B + threadIdx.x;
    if (i < N_NODES) {
        int o = d_off[i] + d_bsum2[blockIdx.x];
        d_off[i] = o;
        d_pos[i] = o;
    }
}

__global__ void k_fill(const int* __restrict__ src, const int* __restrict__ dst) {
    int e = blockIdx.x * blockDim.x + threadIdx.x;
    if (e >= N_EDGES) return;
    int p = atomicAdd(&d_pos[dst[e]], 1);
    d_csrc[p] = src[e];
}

// ---------------- K3: fused softmax + aggregate + normalize + head-mean ----
__device__ __forceinline__ void agg_edge(int s, int hd, int l, float qv,
                                         float4& acc, float& den) {
    const float kk = d_kk[s * N_HEADS + hd];
    const float4 hv = *(const float4*)&d_h[(size_t)s * HF + l * 4];
    float c = kk + qv; c = (c >= 0.f) ? c : NEG_SLOPE * c;
    const float e = __expf(c);
    acc.x = fmaf(e, hv.x, acc.x); acc.y = fmaf(e, hv.y, acc.y);
    acc.z = fmaf(e, hv.z, acc.z); acc.w = fmaf(e, hv.w, acc.w);
    den += e;
}

__global__ __launch_bounds__(128) void k_agg(float* __restrict__ out) {
    const int n = blockIdx.x * 4 + (threadIdx.x >> 5);
    if (n >= N_NODES) return;
    const int l  = threadIdx.x & 31;
    const int hd = l >> 2;

    const float qv    = d_q[n * N_HEADS + hd];
    const int   start = d_off[n];
    const int   deg   = d_deg[n];

    float4 acc = make_float4(0.f, 0.f, 0.f, 0.f);
    float  den = 0.f;

    int j = 0;
    for (; j + 3 < deg; j += 4) {
        const int s0 = d_csrc[start + j];
        const int s1 = d_csrc[start + j + 1];
        const int s2 = d_csrc[start + j + 2];
        const int s3 = d_csrc[start + j + 3];
        agg_edge(s0, hd, l, qv, acc, den);
        agg_edge(s1, hd, l, qv, acc, den);
        agg_edge(s2, hd, l, qv, acc, den);
        agg_edge(s3, hd, l, qv, acc, den);
    }
    for (; j < deg; ++j)
        agg_edge(d_csrc[start + j], hd, l, qv, acc, den);

    const float inv = (deg > 0) ? 1.0f / den : 0.0f;
    acc.x *= inv; acc.y *= inv; acc.z *= inv; acc.w *= inv;

#pragma unroll
    for (int off = 4; off < 32; off <<= 1) {
        acc.x += __shfl_xor_sync(0xffffffff, acc.x, off);
        acc.y += __shfl_xor_sync(0xffffffff, acc.y, off);
        acc.z += __shfl_xor_sync(0xffffffff, acc.z, off);
        acc.w += __shfl_xor_sync(0xffffffff, acc.w, off);
    }

    if (l < 4) {
        float4 r;
        r.x = acc.x * (1.0f / N_HEADS);
        r.y = acc.y * (1.0f / N_HEADS);
        r.z = acc.z * (1.0f / N_HEADS);
        r.w = acc.w * (1.0f / N_HEADS);
        *(float4*)&out[(size_t)n * OUT_FEAT + l * 4] = r;
    }
}

// ---------------- stream/event infrastructure (created once, host-side) ----
static cudaStream_t g_s2 = 0;
static cudaEvent_t  g_evFork = 0, g_evJoin = 0;
namespace {
struct StreamInit {
    StreamInit() {
        cudaStreamCreateWithFlags(&g_s2, cudaStreamNonBlocking);
        cudaEventCreateWithFlags(&g_evFork, cudaEventDisableTiming);
        cudaEventCreateWithFlags(&g_evJoin, cudaEventDisableTiming);
    }
};
static StreamInit g_stream_init;
}

// ---------------- launch ----------------
extern "C" void kernel_launch(void* const* d_in, const int* in_sizes, int n_in,
                              void* d_out, int out_size) {
    const float* x   = (const float*)d_in[0];
    const int*   src = (const int*)d_in[1];
    const int*   dst = (const int*)d_in[2];
    const float* Wv  = (const float*)d_in[3];
    const float* bv  = (const float*)d_in[4];
    const float* Wq  = (const float*)d_in[5];
    const float* bq  = (const float*)d_in[6];
    const float* Wk  = (const float*)d_in[7];
    const float* bk  = (const float*)d_in[8];
    float* out = (float*)d_out;

    // fork: branch B (CSR build) on g_s2, branch A (gemm+qk) on stream 0
    cudaEventRecord(g_evFork, 0);
    cudaStreamWaitEvent(g_s2, g_evFork, 0);

    // Branch A (default stream): projections
    k_gemm <<<(N_NODES + GBM - 1) / GBM, 256>>>(x, Wv, bv);
    k_qk   <<<(N_NODES + 7) / 8, 128>>>(Wq, bq, Wk, bk);

    // Branch B (g_s2): CSR build
    k_init <<<(N_NODES + 255) / 256, 256, 0, g_s2>>>();
    k_count<<<(N_EDGES + 255) / 256, 256, 0, g_s2>>>(dst);
    k_scan1<<<NB1, SCAN_B, 0, g_s2>>>();
    k_scan2<<<1, 256, 0, g_s2>>>();
    k_scan3<<<NB1, SCAN_B, 0, g_s2>>>();
    k_fill <<<(N_EDGES + 255) / 256, 256, 0, g_s2>>>(src, dst);

    // join
    cudaEventRecord(g_evJoin, g_s2);
    cudaStreamWaitEvent(0, g_evJoin, 0);

    k_agg  <<<(N_NODES + 3) / 4, 128>>>(out);
}

// round 16
// speedup vs baseline: 1.6727x; 1.0568x over previous
#include <cuda_runtime.h>
#include <math.h>

#define N_NODES   100000
#define N_EDGES   1600000
#define IN_FEAT   128
#define N_HEADS   8
#define OUT_FEAT  16
#define HF        128
#define NEG_SLOPE 0.2f

#define SCAN_B    512
#define NB1       ((N_NODES + SCAN_B - 1) / SCAN_B)   // 196

// ---------------- device scratch ----------------
__device__ float d_h   [N_NODES * HF];
__device__ float d_q   [N_NODES * N_HEADS];
__device__ float d_kk  [N_NODES * N_HEADS];
__device__ float d_Wc  [IN_FEAT * 16];      // combined [Wv@Wq | Wv@Wk]  (col-block q|k)
__device__ float d_bc  [16];                // combined biases
__device__ int   d_deg [N_NODES];
__device__ int   d_off [N_NODES];
__device__ int   d_pos [N_NODES];
__device__ int   d_csrc[N_EDGES];
__device__ int   d_bsum[NB1];
__device__ int   d_bsum2[NB1];

// ---------------- K0: init ----------------
__global__ void k_init() {
    int i = blockIdx.x * blockDim.x + threadIdx.x;
    if (i < N_NODES) d_deg[i] = 0;
}

// ---------------- helpers ----------------
__device__ __forceinline__ unsigned f2tf(float f) {
    unsigned r;
    asm("cvt.rna.tf32.f32 %0, %1;" : "=r"(r) : "f"(f));
    return r;
}

// ---------------- K1: tf32 tensor-core GEMM  h = x @ Wv + bv ----------------
#define GBM 128
#define GBK 32
__global__ __launch_bounds__(256) void k_gemm(const float* __restrict__ x,
                                              const float* __restrict__ Wv,
                                              const float* __restrict__ bv) {
    __shared__ float Xs[GBM][36];
    __shared__ float Ws[GBK][136];

    const int tid  = threadIdx.x;
    const int lane = tid & 31;
    const int warp = tid >> 5;
    const int bm   = blockIdx.x * GBM;

    const int warp_m = (warp & 3) * 32;
    const int warp_n = (warp >> 2) * 64;

    const int lq = lane >> 2;
    const int lr = lane & 3;

    float c[2][8][4];
#pragma unroll
    for (int mt = 0; mt < 2; ++mt)
#pragma unroll
        for (int nt = 0; nt < 8; ++nt)
#pragma unroll
            for (int j = 0; j < 4; ++j) c[mt][nt][j] = 0.0f;

    for (int k0 = 0; k0 < IN_FEAT; k0 += GBK) {
#pragma unroll
        for (int i = 0; i < 4; ++i) {
            int fid = tid + i * 256;
            int row = fid >> 3;
            int c4  = fid & 7;
            int node = bm + row;
            float4 v = make_float4(0.f, 0.f, 0.f, 0.f);
            if (node < N_NODES)
                v = *(const float4*)&x[(size_t)node * IN_FEAT + k0 + c4 * 4];
            float4 t;
            t.x = __uint_as_float(f2tf(v.x));
            t.y = __uint_as_float(f2tf(v.y));
            t.z = __uint_as_float(f2tf(v.z));
            t.w = __uint_as_float(f2tf(v.w));
            *(float4*)&Xs[row][c4 * 4] = t;
        }
#pragma unroll
        for (int i = 0; i < 4; ++i) {
            int fid = tid + i * 256;
            int row = fid >> 5;
            int c4  = fid & 31;
            float4 v = *(const float4*)&Wv[(size_t)(k0 + row) * HF + c4 * 4];
            float4 t;
            t.x = __uint_as_float(f2tf(v.x));
            t.y = __uint_as_float(f2tf(v.y));
            t.z = __uint_as_float(f2tf(v.z));
            t.w = __uint_as_float(f2tf(v.w));
            *(float4*)&Ws[row][c4 * 4] = t;
        }
        __syncthreads();

#pragma unroll
        for (int ks = 0; ks < GBK / 8; ++ks) {
            const int kc = ks * 8;
            unsigned a[2][4];
#pragma unroll
            for (int mt = 0; mt < 2; ++mt) {
                const int m0 = warp_m + mt * 16;
                a[mt][0] = __float_as_uint(Xs[m0 + lq    ][kc + lr    ]);
                a[mt][1] = __float_as_uint(Xs[m0 + 8 + lq][kc + lr    ]);
                a[mt][2] = __float_as_uint(Xs[m0 + lq    ][kc + 4 + lr]);
                a[mt][3] = __float_as_uint(Xs[m0 + 8 + lq][kc + 4 + lr]);
            }
#pragma unroll
            for (int nt = 0; nt < 8; ++nt) {
                const int n0 = warp_n + nt * 8;
                unsigned b0 = __float_as_uint(Ws[kc + lr    ][n0 + lq]);
                unsigned b1 = __float_as_uint(Ws[kc + 4 + lr][n0 + lq]);
#pragma unroll
                for (int mt = 0; mt < 2; ++mt) {
                    asm volatile(
                        "mma.sync.aligned.m16n8k8.row.col.f32.tf32.tf32.f32 "
                        "{%0,%1,%2,%3}, {%4,%5,%6,%7}, {%8,%9}, {%0,%1,%2,%3};\n"
                        : "+f"(c[mt][nt][0]), "+f"(c[mt][nt][1]),
                          "+f"(c[mt][nt][2]), "+f"(c[mt][nt][3])
                        : "r"(a[mt][0]), "r"(a[mt][1]), "r"(a[mt][2]), "r"(a[mt][3]),
                          "r"(b0), "r"(b1));
                }
            }
        }
        __syncthreads();
    }

#pragma unroll
    for (int nt = 0; nt < 8; ++nt) {
        const int col = warp_n + nt * 8 + lr * 2;
        const float2 bias = *(const float2*)&bv[col];
#pragma unroll
        for (int mt = 0; mt < 2; ++mt) {
            const int r0 = bm + warp_m + mt * 16 + lq;
            if (r0 < N_NODES) {
                float2 v = make_float2(c[mt][nt][0] + bias.x, c[mt][nt][1] + bias.y);
                *(float2*)&d_h[(size_t)r0 * HF + col] = v;
            }
            const int r1 = r0 + 8;
            if (r1 < N_NODES) {
                float2 v = make_float2(c[mt][nt][2] + bias.x, c[mt][nt][3] + bias.y);
                *(float2*)&d_h[(size_t)r1 * HF + col] = v;
            }
        }
    }
}

// ---------------- K2a: combine weights  Wc = [Wv@Wq | Wv@Wk], bc ----------
__global__ __launch_bounds__(256) void k_combine(const float* __restrict__ Wv,
                                                 const float* __restrict__ bv,
                                                 const float* __restrict__ Wq,
                                                 const float* __restrict__ bq,
                                                 const float* __restrict__ Wk,
                                                 const float* __restrict__ bk) {
    __shared__ float Wqs[HF * N_HEADS];
    __shared__ float Wks[HF * N_HEADS];
    const int t = threadIdx.x;
#pragma unroll
    for (int i = 0; i < 4; ++i) {
        Wqs[t + i * 256] = Wq[t + i * 256];
        Wks[t + i * 256] = Wk[t + i * 256];
    }
    __syncthreads();

    const bool isK = (t >= 128);
    const int  i   = t & 127;
    const float* Wsm = isK ? Wks : Wqs;
    float acc[N_HEADS];
#pragma unroll
    for (int hd = 0; hd < N_HEADS; ++hd) acc[hd] = 0.0f;
    for (int j = 0; j < HF; ++j) {
        const float wv = Wv[(size_t)i * HF + j];   // Wv[i][j] : row i of Wv... careful
        // NOTE: Wv is [IN_FEAT, HF] row-major; we need Wc[i][hd] = sum_j Wv[i][j] * Wq[j][hd]
#pragma unroll
        for (int hd = 0; hd < N_HEADS; ++hd)
            acc[hd] = fmaf(wv, Wsm[j * N_HEADS + hd], acc[hd]);
    }
#pragma unroll
    for (int hd = 0; hd < N_HEADS; ++hd)
        d_Wc[i * 16 + (isK ? 8 : 0) + hd] = acc[hd];

    // combined biases: bc = b + bv @ W  (threads 0..15)
    if (t < 16) {
        const bool kk = (t >= 8);
        const int hd = t & 7;
        const float* W = kk ? Wks : Wqs;
        float s = kk ? bk[hd] : bq[hd];
        for (int j = 0; j < HF; ++j)
            s = fmaf(bv[j], W[j * N_HEADS + hd], s);
        d_bc[t] = s;
    }
}

// ---------------- K2b: q/k directly from x  (8 nodes / 128-thread block) ----
__global__ __launch_bounds__(128) void k_qk2(const float* __restrict__ x) {
    __shared__ float xs[8][HF];
    __shared__ float Wcs[HF * 16];
    __shared__ float bcs[16];

    const int t = threadIdx.x;
    const int nb = blockIdx.x * 8;

#pragma unroll
    for (int i = 0; i < 16; ++i)
        Wcs[t + i * 128] = d_Wc[t + i * 128];
    if (t < 16) bcs[t] = d_bc[t];
#pragma unroll
    for (int i = 0; i < 8; ++i) {
        int idx = t + i * 128;
        int nl = idx >> 7;
        int j  = idx & 127;
        int node = nb + nl;
        xs[nl][j] = (node < N_NODES) ? x[(size_t)node * IN_FEAT + j] : 0.0f;
    }
    __syncthreads();

    const int nl = t >> 4;
    const int id = t & 15;
    const int node = nb + nl;
    if (node >= N_NODES) return;

    float s = bcs[id];
#pragma unroll 16
    for (int j = 0; j < HF; ++j)
        s = fmaf(xs[nl][j], Wcs[j * 16 + id], s);

    if (id < 8) d_q [node * N_HEADS + id] = s;
    else        d_kk[node * N_HEADS + (id - 8)] = s;
}

// ---------------- CSR build (vectorized) ----------------
__global__ void k_count(const int* __restrict__ dst) {
    int i = blockIdx.x * blockDim.x + threadIdx.x;
    if (i >= N_EDGES / 4) return;
    int4 d = ((const int4*)dst)[i];
    atomicAdd(&d_deg[d.x], 1);
    atomicAdd(&d_deg[d.y], 1);
    atomicAdd(&d_deg[d.z], 1);
    atomicAdd(&d_deg[d.w], 1);
}

__global__ __launch_bounds__(SCAN_B) void k_scan1() {
    __shared__ int tmp[2][SCAN_B];
    const int t = threadIdx.x;
    const int i = blockIdx.x * SCAN_B + t;
    int v = (i < N_NODES) ? d_deg[i] : 0;
    tmp[0][t] = v;
    __syncthreads();
    int pp = 0;
    for (int off = 1; off < SCAN_B; off <<= 1) {
        int xv = tmp[pp][t];
        if (t >= off) xv += tmp[pp][t - off];
        tmp[pp ^ 1][t] = xv;
        pp ^= 1;
        __syncthreads();
    }
    int incl = tmp[pp][t];
    if (i < N_NODES) d_off[i] = incl - v;
    if (t == SCAN_B - 1) d_bsum[blockIdx.x] = incl;
}

__global__ __launch_bounds__(256) void k_scan2() {
    __shared__ int tmp[2][256];
    const int t = threadIdx.x;
    int v = (t < NB1) ? d_bsum[t] : 0;
    tmp[0][t] = v;
    __syncthreads();
    int pp = 0;
    for (int off = 1; off < 256; off <<= 1) {
        int xv = tmp[pp][t];
        if (t >= off) xv += tmp[pp][t - off];
        tmp[pp ^ 1][t] = xv;
        pp ^= 1;
        __syncthreads();
    }
    if (t < NB1) d_bsum2[t] = tmp[pp][t] - v;
}

__global__ __launch_bounds__(SCAN_B) void k_scan3() {
    const int i = blockIdx.x * SCAN_B + threadIdx.x;
    if (i < N_NODES) {
        int o = d_off[i] + d_bsum2[blockIdx.x];
        d_off[i] = o;
        d_pos[i] = o;
    }
}

__global__ void k_fill(const int* __restrict__ src, const int* __restrict__ dst) {
    int i = blockIdx.x * blockDim.x + threadIdx.x;
    if (i >= N_EDGES / 4) return;
    int4 d = ((const int4*)dst)[i];
    int4 s = ((const int4*)src)[i];
    d_csrc[atomicAdd(&d_pos[d.x], 1)] = s.x;
    d_csrc[atomicAdd(&d_pos[d.y], 1)] = s.y;
    d_csrc[atomicAdd(&d_pos[d.z], 1)] = s.z;
    d_csrc[atomicAdd(&d_pos[d.w], 1)] = s.w;
}

// ---------------- K3: fused softmax + aggregate + normalize + head-mean ----
__device__ __forceinline__ void agg_edge(int s, int hd, int l, float qv,
                                         float4& acc, float& den) {
    const float kk = d_kk[s * N_HEADS + hd];
    const float4 hv = *(const float4*)&d_h[(size_t)s * HF + l * 4];
    float c = kk + qv; c = (c >= 0.f) ? c : NEG_SLOPE * c;
    const float e = __expf(c);
    acc.x = fmaf(e, hv.x, acc.x); acc.y = fmaf(e, hv.y, acc.y);
    acc.z = fmaf(e, hv.z, acc.z); acc.w = fmaf(e, hv.w, acc.w);
    den += e;
}

__global__ __launch_bounds__(128) void k_agg(float* __restrict__ out) {
    const int n = blockIdx.x * 4 + (threadIdx.x >> 5);
    if (n >= N_NODES) return;
    const int l  = threadIdx.x & 31;
    const int hd = l >> 2;

    const float qv    = d_q[n * N_HEADS + hd];
    const int   start = d_off[n];
    const int   deg   = d_deg[n];

    float4 acc = make_float4(0.f, 0.f, 0.f, 0.f);
    float  den = 0.f;

    int j = 0;
    for (; j + 3 < deg; j += 4) {
        const int s0 = d_csrc[start + j];
        const int s1 = d_csrc[start + j + 1];
        const int s2 = d_csrc[start + j + 2];
        const int s3 = d_csrc[start + j + 3];
        agg_edge(s0, hd, l, qv, acc, den);
        agg_edge(s1, hd, l, qv, acc, den);
        agg_edge(s2, hd, l, qv, acc, den);
        agg_edge(s3, hd, l, qv, acc, den);
    }
    for (; j < deg; ++j)
        agg_edge(d_csrc[start + j], hd, l, qv, acc, den);

    const float inv = (deg > 0) ? 1.0f / den : 0.0f;
    acc.x *= inv; acc.y *= inv; acc.z *= inv; acc.w *= inv;

#pragma unroll
    for (int off = 4; off < 32; off <<= 1) {
        acc.x += __shfl_xor_sync(0xffffffff, acc.x, off);
        acc.y += __shfl_xor_sync(0xffffffff, acc.y, off);
        acc.z += __shfl_xor_sync(0xffffffff, acc.z, off);
        acc.w += __shfl_xor_sync(0xffffffff, acc.w, off);
    }

    if (l < 4) {
        float4 r;
        r.x = acc.x * (1.0f / N_HEADS);
        r.y = acc.y * (1.0f / N_HEADS);
        r.z = acc.z * (1.0f / N_HEADS);
        r.w = acc.w * (1.0f / N_HEADS);
        *(float4*)&out[(size_t)n * OUT_FEAT + l * 4] = r;
    }
}

// ---------------- stream/event infrastructure (created once, host-side) ----
static cudaStream_t g_s2 = 0, g_s3 = 0;
static cudaEvent_t  g_evFork = 0, g_evJoin2 = 0, g_evJoin3 = 0;
namespace {
struct StreamInit {
    StreamInit() {
        cudaStreamCreateWithFlags(&g_s2, cudaStreamNonBlocking);
        cudaStreamCreateWithFlags(&g_s3, cudaStreamNonBlocking);
        cudaEventCreateWithFlags(&g_evFork, cudaEventDisableTiming);
        cudaEventCreateWithFlags(&g_evJoin2, cudaEventDisableTiming);
        cudaEventCreateWithFlags(&g_evJoin3, cudaEventDisableTiming);
    }
};
static StreamInit g_stream_init;
}

// ---------------- launch ----------------
extern "C" void kernel_launch(void* const* d_in, const int* in_sizes, int n_in,
                              void* d_out, int out_size) {
    const float* x   = (const float*)d_in[0];
    const int*   src = (const int*)d_in[1];
    const int*   dst = (const int*)d_in[2];
    const float* Wv  = (const float*)d_in[3];
    const float* bv  = (const float*)d_in[4];
    const float* Wq  = (const float*)d_in[5];
    const float* bq  = (const float*)d_in[6];
    const float* Wk  = (const float*)d_in[7];
    const float* bk  = (const float*)d_in[8];
    float* out = (float*)d_out;

    cudaEventRecord(g_evFork, 0);
    cudaStreamWaitEvent(g_s2, g_evFork, 0);
    cudaStreamWaitEvent(g_s3, g_evFork, 0);

    // Branch A (stream 0): h projection
    k_gemm   <<<(N_NODES + GBM - 1) / GBM, 256>>>(x, Wv, bv);

    // Branch B (g_s2): CSR build
    k_init   <<<(N_NODES + 255) / 256, 256, 0, g_s2>>>();
    k_count  <<<(N_EDGES / 4 + 255) / 256, 256, 0, g_s2>>>(dst);
    k_scan1  <<<NB1, SCAN_B, 0, g_s2>>>();
    k_scan2  <<<1, 256, 0, g_s2>>>();
    k_scan3  <<<NB1, SCAN_B, 0, g_s2>>>();
    k_fill   <<<(N_EDGES / 4 + 255) / 256, 256, 0, g_s2>>>(src, dst);

    // Branch C (g_s3): q/k from x via combined weights
    k_combine<<<1, 256, 0, g_s3>>>(Wv, bv, Wq, bq, Wk, bk);
    k_qk2    <<<(N_NODES + 7) / 8, 128, 0, g_s3>>>(x);

    // join all into stream 0
    cudaEventRecord(g_evJoin2, g_s2);
    cudaStreamWaitEvent(0, g_evJoin2, 0);
    cudaEventRecord(g_evJoin3, g_s3);
    cudaStreamWaitEvent(0, g_evJoin3, 0);

    k_agg<<<(N_NODES + 3) / 4, 128>>>(out);
}